// round 13
// baseline (speedup 1.0000x reference)
#include <cuda_runtime.h>
#include <cuda_bf16.h>
#include <cstdint>

#define B 64
#define S 128
#define NQ 2000
#define C 128
#define K 64
#define DE 64
#define DC 64
#define HP 68   // padded row stride for h rows in smem (16B-aligned rows)
#define WP 76   // padded row stride for transposed weights

typedef unsigned long long ull;

// -------- scratch (device globals; no allocation allowed) --------
__device__ float d_AL[NQ * 2 * K];
__device__ float d_diffQ[NQ * C];
__device__ float d_discQ[NQ];
__device__ float d_P2[B * (S - 1) * K];
__device__ float d_P3[B * (S - 1) * K];

__device__ __forceinline__ float fsig(float x) {
    return __fdividef(1.0f, 1.0f + __expf(-x));
}
__device__ __forceinline__ ull fma2(ull a, ull b, ull c) {
    ull d;
    asm("fma.rn.f32x2 %0,%1,%2,%3;" : "=l"(d) : "l"(a), "l"(b), "l"(c));
    return d;
}
__device__ __forceinline__ float f2sum(ull v) {
    float lo, hi;
    asm("mov.b64 {%0,%1},%2;" : "=f"(lo), "=f"(hi) : "l"(v));
    return lo + hi;
}
__device__ __forceinline__ ull packf2(float lo, float hi) {
    ull v;
    asm("mov.b64 %0,{%1,%2};" : "=l"(v) : "f"(lo), "f"(hi));
    return v;
}
__device__ __forceinline__ uint32_t s2u(const void* p) {
    uint32_t a;
    asm("{ .reg .u64 t; cvta.to.shared.u64 t, %1; cvt.u32.u64 %0, t; }" : "=r"(a) : "l"(p));
    return a;
}
__device__ __forceinline__ uint32_t ctarank() {
    uint32_t r;
    asm("mov.u32 %0, %%cluster_ctarank;" : "=r"(r));
    return r;
}
__device__ __forceinline__ void mbar_init(uint32_t a, uint32_t cnt) {
    asm volatile("mbarrier.init.shared.b64 [%0], %1;" :: "r"(a), "r"(cnt) : "memory");
}
__device__ __forceinline__ void mbar_wait_acq(uint32_t a, uint32_t par) {
    asm volatile(
        "{\n\t.reg .pred P;\n\t"
        "WL_%=:\n\t"
        "mbarrier.try_wait.parity.acquire.cluster.shared::cta.b64 P, [%0], %1, 0x989680;\n\t"
        "@!P bra WL_%=;\n\t}"
        :: "r"(a), "r"(par) : "memory");
}
__device__ __forceinline__ void remote_st64(uint32_t a, uint32_t rank, ull v) {
    asm volatile(
        "{\n\t.reg .b32 r;\n\t"
        "mapa.shared::cluster.u32 r, %0, %1;\n\t"
        "st.shared::cluster.b64 [r], %2;\n\t}"
        :: "r"(a), "r"(rank), "l"(v) : "memory");
}
__device__ __forceinline__ void remote_st32(uint32_t a, uint32_t rank, float v) {
    asm volatile(
        "{\n\t.reg .b32 r;\n\t"
        "mapa.shared::cluster.u32 r, %0, %1;\n\t"
        "st.shared::cluster.b32 [r], %2;\n\t}"
        :: "r"(a), "r"(rank), "f"(v) : "memory");
}
__device__ __forceinline__ void remote_arrive(uint32_t a, uint32_t rank) {
    asm volatile(
        "{\n\t.reg .b32 r;\n\t"
        "mapa.shared::cluster.u32 r, %0, %1;\n\t"
        "mbarrier.arrive.release.cluster.shared::cluster.b64 _, [r];\n\t}"
        :: "r"(a), "r"(rank) : "memory");
}
#define CLUSTER_SYNC_() do { \
    asm volatile("barrier.cluster.arrive.aligned;" ::: "memory"); \
    asm volatile("barrier.cluster.wait.aligned;" ::: "memory"); \
} while (0)

// -------- precompute kernels --------
__global__ void k_al(const float* __restrict__ Eq, const float* __restrict__ Ec,
                     const float* __restrict__ W1, const float* __restrict__ b1) {
    int q = blockIdx.x;
    int tid = threadIdx.x;
    __shared__ float eq[DE];
    if (tid < DE) eq[tid] = Eq[q * DE + tid];
    __syncthreads();
    int corr = tid >> 6;
    int k = tid & 63;
    float a = b1[k];
#pragma unroll 4
    for (int d = 0; d < DE; d++) a = fmaf(eq[d], W1[d * K + k], a);
#pragma unroll 4
    for (int d = 0; d < DC; d++) a = fmaf(Ec[corr * DC + d], W1[(DE + d) * K + k], a);
    d_AL[(q * 2 + corr) * K + k] = a;
}

__global__ void k_dq(const float* __restrict__ Eq, const float* __restrict__ Wdiff,
                     const float* __restrict__ bdiff, const float* __restrict__ Wdisc,
                     const float* __restrict__ bdisc, const float* __restrict__ qmat) {
    int q = blockIdx.x;
    int c = threadIdx.x;
    __shared__ float eq[DE];
    if (c < DE) eq[c] = Eq[q * DE + c];
    __syncthreads();
    float a = bdiff[c];
#pragma unroll 4
    for (int d = 0; d < DE; d++) a = fmaf(eq[d], Wdiff[d * C + c], a);
    d_diffQ[q * C + c] = fsig(a) * qmat[q * C + c];
    if (c == 0) {
        float dd = bdisc[0];
        for (int d = 0; d < DE; d++) dd = fmaf(eq[d], Wdisc[d], dd);
        d_discQ[q] = fsig(dd) * 5.0f;
    }
}

__global__ void k_p23(const int* __restrict__ qseq, const int* __restrict__ cseq,
                      const float* __restrict__ W2, const float* __restrict__ W3,
                      const float* __restrict__ b2, const float* __restrict__ b3) {
    int blk = blockIdx.x;
    int b = blk / (S - 1);
    int t = blk % (S - 1);
    __shared__ float lp[K], lc[K];
    int tid = threadIdx.x;
    if (tid < K) {
        int qc = qseq[b * S + t], cc = cseq[b * S + t];
        lc[tid] = d_AL[(qc * 2 + cc) * K + tid];
        if (t > 0) {
            int qp = qseq[b * S + t - 1], cp = cseq[b * S + t - 1];
            lp[tid] = d_AL[(qp * 2 + cp) * K + tid];
        } else {
            lp[tid] = 0.0f;
        }
    }
    __syncthreads();
    int which = tid >> 6;
    int k = tid & 63;
    const float* W = which ? W3 : W2;
    float a = which ? b3[k] : b2[k];
#pragma unroll 4
    for (int j = 0; j < K; j++) a = fmaf(lp[j], W[j * K + k], a);
#pragma unroll 4
    for (int j = 0; j < K; j++) a = fmaf(lc[j], W[(K + j) * K + k], a);
    float* dst = which ? d_P3 : d_P2;
    dst[blk * K + k] = a;
}

// -------- main kernel: cluster of 2 CTAs per batch (c-split), 512 threads --------
// ALL 16 warps matmul; asymmetric rows per pair: pair0 (P1 warps) 4 rows,
// pair1 (y + prefetch warps) 6 rows, pairs 2-7 9 rows each.
struct __align__(16) Smem {
    float W4bT[K * WP];      // [k][j]
    float W2hT[K * WP];      // [k][j]
    float W3hT[K * WP];      // [k][j]
    float hs[2][64 * HP];    // own 64 c-rows, double buffered
    float part[8][K];        // per-pair h_tilde partials (local)
    float htld[K];           // reduced OWN h_tilde partial (for P1 own-dot)
    float htpeer[2][K];      // peer's h_tilde partial (slot = step parity)
    float LGs[K];
    float lgt[K];
    float qrow[3][C];
    float diffr[2][C];
    float Wabs[K];
    float b4s[K];
    float discs[2];
    float ypeer[2];
    ull mb_ht[2];
    ull mb_y[2];
};

__global__ void __launch_bounds__(512, 1) __cluster_dims__(2, 1, 1)
lpkt_main(const int* __restrict__ qseq, const float* __restrict__ qmat,
          const float* __restrict__ h0,
          const float* __restrict__ W2, const float* __restrict__ W3,
          const float* __restrict__ W4, const float* __restrict__ b4,
          const float* __restrict__ Wab, const float* __restrict__ bab,
          float* __restrict__ out) {
    extern __shared__ char raw[];
    Smem* s = (Smem*)raw;
    const int b = blockIdx.x >> 1;
    const uint32_t rank = ctarank();
    const uint32_t peer = rank ^ 1u;
    const int tid = threadIdx.x;
    const int lane = tid & 31;
    const int wid = tid >> 5;                 // 0..15
    const int kk = 32 * (wid & 1) + lane;     // owned k column
    const int pr = wid >> 1;                  // pair index 0..7
    const int r0 = (pr == 0) ? 0 : (pr == 1) ? 4 : 10 + 9 * (pr - 2);
    const int cnt = (pr == 0) ? 4 : (pr == 1) ? 6 : 9;
    const float bab0 = __ldg(bab);

    // ---- W4 top block column -> registers (loop-invariant, reused 127 steps) ----
    ull wreg[32];
#pragma unroll
    for (int q = 0; q < 32; q++)
        wreg[q] = packf2(W4[(2 * q) * K + kk], W4[(2 * q + 1) * K + kk]);

    // ---- init smem ----
    for (int i = tid; i < K * K; i += 512) {
        int j = i & 63, k = i >> 6;
        s->W4bT[k * WP + j] = W4[(K + j) * K + k];
        s->W2hT[k * WP + j] = W2[(128 + j) * K + k];
        s->W3hT[k * WP + j] = W3[(128 + j) * K + k];
    }
    for (int i = tid; i < 64 * K; i += 512) {
        int c = i >> 6, k = i & 63;
        s->hs[0][c * HP + k] = h0[(64 * (int)rank + c) * K + k];
    }
    if (tid < K) { s->Wabs[tid] = Wab[tid]; s->b4s[tid] = b4[tid]; }
    if (tid < C) {
        int q0 = qseq[b * S + 0], q1 = qseq[b * S + 1];
        s->qrow[0][tid] = qmat[q0 * C + tid];
        s->qrow[1][tid] = qmat[q1 * C + tid];
    }
    if (tid == 0) {
        if (rank == 0) out[b * S] = 0.0f;
        mbar_init(s2u(&s->mb_ht[0]), 16);
        mbar_init(s2u(&s->mb_ht[1]), 16);
        mbar_init(s2u(&s->mb_y[0]), 1);
        mbar_init(s2u(&s->mb_y[1]), 1);
    }
    float a2pre = 0.0f, a3pre = 0.0f;
    if (tid < K) {
        a2pre = d_P2[(b * (S - 1)) * K + tid];
        a3pre = d_P3[(b * (S - 1)) * K + tid];
    }
    __syncthreads();
    // h_tilde0 own partial -> part[0]; part[1..7] = 0
    if (tid < K) {
        float acc0 = 0.0f, acc1 = 0.0f;
        for (int c = 0; c < 64; c += 2) {
            acc0 = fmaf(s->qrow[0][64 * rank + c], s->hs[0][c * HP + tid], acc0);
            acc1 = fmaf(s->qrow[0][64 * rank + c + 1], s->hs[0][(c + 1) * HP + tid], acc1);
        }
        s->part[0][tid] = acc0 + acc1;
#pragma unroll
        for (int gg = 1; gg < 8; gg++) s->part[gg][tid] = 0.0f;
    }
    __syncthreads();
    CLUSTER_SYNC_();   // mbarriers initialized in both CTAs; part[] visible
    // initial send: h_tilde0 partial -> peer slot 0
    if (wid == 13 && lane < 16) {
        int base = lane * 4;
        float4 p = *(const float4*)&s->part[0][base];
        uint32_t dst = s2u(&s->htpeer[0][base]);
        remote_st64(dst, peer, packf2(p.x, p.y));
        remote_st64(dst + 8, peer, packf2(p.z, p.w));
        remote_arrive(s2u(&s->mb_ht[0]), peer);
    }

    float ypprev = 0.0f;

    for (int t = 0; t < S - 1; t++) {
        const int t3 = t % 3;
        const int t3n = (t + 1) % 3;
        const int cb = t & 1;
        const int nb = cb ^ 1;
        const float* __restrict__ hcur = s->hs[cb];

        // ---- side phases first (then EVERY warp runs its matmul slice) ----
        if (tid < 64) {
            // ==== P1: own-reduce + own-dot first (hides peer DSMEM latency) ====
            const int k = tid;
            float hsum = s->part[0][k];
#pragma unroll
            for (int gg = 1; gg < 8; gg++) hsum += s->part[gg][k];
            s->htld[k] = hsum;
            asm volatile("bar.sync 1, 64;" ::: "memory");
            ull A2a = 0, A2b = 0, A3a = 0, A3b = 0;
            const float* w2p = s->W2hT + k * WP;
            const float* w3p = s->W3hT + k * WP;
#pragma unroll
            for (int q = 0; q < 16; q++) {
                ulonglong2 hp = *(const ulonglong2*)(s->htld + 4 * q);
                ulonglong2 w2v = *(const ulonglong2*)(w2p + 4 * q);
                ulonglong2 w3v = *(const ulonglong2*)(w3p + 4 * q);
                A2a = fma2(hp.x, w2v.x, A2a); A2b = fma2(hp.y, w2v.y, A2b);
                A3a = fma2(hp.x, w3v.x, A3a); A3b = fma2(hp.y, w3v.y, A3b);
            }
            // wait for peer's partial and fold it in
            mbar_wait_acq(s2u(&s->mb_ht[cb]), (uint32_t)((t >> 1) & 1));
#pragma unroll
            for (int q = 0; q < 16; q++) {
                ulonglong2 hp = *(const ulonglong2*)(s->htpeer[cb] + 4 * q);
                ulonglong2 w2v = *(const ulonglong2*)(w2p + 4 * q);
                ulonglong2 w3v = *(const ulonglong2*)(w3p + 4 * q);
                A2a = fma2(hp.x, w2v.x, A2a); A2b = fma2(hp.y, w2v.y, A2b);
                A3a = fma2(hp.x, w3v.x, A3a); A3b = fma2(hp.y, w3v.y, A3b);
            }
            float a2 = a2pre + f2sum(A2a) + f2sum(A2b);
            float a3 = a3pre + f2sum(A3a) + f2sum(A3b);
            s->LGs[k] = fsig(a3) * fsig(2.0f * a2);   // (tanh+1)/2 == sigmoid(2x)
            asm volatile("bar.sync 1, 64;" ::: "memory");
            // lgt = b4 + LG @ W4b
            ull La = 0, Lb = 0;
            const float* wbp = s->W4bT + k * WP;
#pragma unroll
            for (int q = 0; q < 16; q++) {
                ulonglong2 lg = *(const ulonglong2*)(s->LGs + 4 * q);
                ulonglong2 w = *(const ulonglong2*)(wbp + 4 * q);
                La = fma2(lg.x, w.x, La); Lb = fma2(lg.y, w.y, Lb);
            }
            s->lgt[k] = s->b4s[k] + f2sum(La) + f2sum(Lb);
            if (t + 1 < S - 1) {
                a2pre = d_P2[(b * (S - 1) + t + 1) * K + tid];
                a3pre = d_P3[(b * (S - 1) + t + 1) * K + tid];
            }
        } else if (wid == 2) {
            // ==== y_t partial over own 64 rows; rank0 flushes out[t-1] ====
            float pt = 0.0f;
            if (t > 0) {
                ull Aa = 0, Ab = 0, Ba = 0, Bb = 0;
                const float* rr0 = hcur + lane * HP;
                const float* rr1 = hcur + (lane + 32) * HP;
#pragma unroll
                for (int q = 0; q < 16; q++) {
                    ulonglong2 wv = *(const ulonglong2*)(s->Wabs + 4 * q);
                    ulonglong2 h0v = *(const ulonglong2*)(rr0 + 4 * q);
                    ulonglong2 h1v = *(const ulonglong2*)(rr1 + 4 * q);
                    Aa = fma2(h0v.x, wv.x, Aa); Ab = fma2(h0v.y, wv.y, Ab);
                    Ba = fma2(h1v.x, wv.x, Ba); Bb = fma2(h1v.y, wv.y, Bb);
                }
                int g0 = 64 * rank + lane, g1 = g0 + 32;
                float abl0 = fsig(f2sum(Aa) + f2sum(Ab) + bab0) * s->qrow[t3][g0];
                float abl1 = fsig(f2sum(Ba) + f2sum(Bb) + bab0) * s->qrow[t3][g1];
                pt = s->discs[cb] *
                     ((abl0 - s->diffr[cb][g0]) + (abl1 - s->diffr[cb][g1]));
#pragma unroll
                for (int off = 16; off; off >>= 1)
                    pt += __shfl_xor_sync(0xffffffffu, pt, off);
            }
            if (rank == 1) {
                if (t > 0 && lane == 0) {
                    remote_st32(s2u(&s->ypeer[cb]), peer, pt);
                    remote_arrive(s2u(&s->mb_y[cb]), peer);
                }
            } else {
                if (t > 1 && lane == 0) {
                    int pb = (t - 1) & 1;
                    mbar_wait_acq(s2u(&s->mb_y[pb]), (uint32_t)(((t - 2) >> 1) & 1));
                    out[b * S + t - 1] = fsig(ypprev + s->ypeer[pb]);
                }
                ypprev = pt;
            }
        } else if (wid == 3) {
            // ==== prefetch next q rows / diff / disc ====
            int t2 = (t + 2 < S) ? (t + 2) : (S - 1);
            int q2v = qseq[b * S + t2];
            int q1v = qseq[b * S + t + 1];
#pragma unroll
            for (int h = 0; h < 2; h++) {
                int i2 = lane + 32 * h;
                *(float2*)(s->qrow[(t + 2) % 3] + 2 * i2) =
                    *(const float2*)(qmat + q2v * C + 2 * i2);
                *(float2*)(s->diffr[nb] + 2 * i2) =
                    *(const float2*)(d_diffQ + q1v * C + 2 * i2);
            }
            if (lane == 0) s->discs[nb] = d_discQ[q1v];
        }

        // ==== gate matmul (ALL warps): weights in regs, h via broadcast LDS ====
        ull acc[9];
#pragma unroll
        for (int r = 0; r < 9; r++) acc[r] = 0ull;
#pragma unroll
        for (int q = 0; q < 16; q++) {
#pragma unroll
            for (int r = 0; r < 9; r++) {
                if (r < cnt) {
                    ulonglong2 hv = *(const ulonglong2*)(hcur + (r0 + r) * HP + 4 * q);
                    acc[r] = fma2(hv.x, wreg[2 * q], acc[r]);
                    acc[r] = fma2(hv.y, wreg[2 * q + 1], acc[r]);
                }
            }
        }
        __syncthreads();   // sync1: LGs/lgt ready, prefetch done

        // ==== epilogue: gamma_f, h update, h_tilde partial ====
        {
            float LGk = s->LGs[kk];
            float lgtk = s->lgt[kk];
            float htn = 0.0f;
            float* __restrict__ hnew = s->hs[nb];
#pragma unroll
            for (int r = 0; r < 9; r++) {
                if (r < cnt) {
                    int c = r0 + r;
                    int gc = 64 * (int)rank + c;
                    float qev = s->qrow[t3][gc];
                    float qnv = s->qrow[t3n][gc];
                    float ho = hcur[c * HP + kk];
                    float a = f2sum(acc[r]) + lgtk;
                    float gf = fsig(a);
                    float v = fmaf(qev, LGk, gf * ho);
                    hnew[c * HP + kk] = v;
                    htn = fmaf(qnv, v, htn);
                }
            }
            s->part[pr][kk] = htn;
        }
        __syncthreads();   // sync2: hnew + part complete

        // ---- send summed h_tilde partial for step t+1 to peer ----
        if (wid == 13 && lane < 16 && t < S - 2) {
            int base = lane * 4;
            float4 p = *(const float4*)&s->part[0][base];
#pragma unroll
            for (int gg = 1; gg < 8; gg++) {
                float4 t4 = *(const float4*)&s->part[gg][base];
                p.x += t4.x; p.y += t4.y; p.z += t4.z; p.w += t4.w;
            }
            uint32_t dst = s2u(&s->htpeer[nb][base]);
            remote_st64(dst, peer, packf2(p.x, p.y));
            remote_st64(dst + 8, peer, packf2(p.z, p.w));
            remote_arrive(s2u(&s->mb_ht[nb]), peer);
        }
    }

    // ==== tail ====
    if (wid == 2) {
        // flush out[S-2] on rank0
        if (rank == 0 && lane == 0) {
            int pb = (S - 2) & 1;   // 0
            mbar_wait_acq(s2u(&s->mb_y[pb]), (uint32_t)(((S - 3) >> 1) & 1));
            out[b * S + (S - 2)] = fsig(ypprev + s->ypeer[pb]);
        }
        // final y_{S-1} on h state hs[1]
        const float* hfin = s->hs[(S - 1) & 1];
        ull Aa = 0, Ab = 0, Ba = 0, Bb = 0;
        const float* rr0 = hfin + lane * HP;
        const float* rr1 = hfin + (lane + 32) * HP;
#pragma unroll
        for (int q = 0; q < 16; q++) {
            ulonglong2 wv = *(const ulonglong2*)(s->Wabs + 4 * q);
            ulonglong2 h0v = *(const ulonglong2*)(rr0 + 4 * q);
            ulonglong2 h1v = *(const ulonglong2*)(rr1 + 4 * q);
            Aa = fma2(h0v.x, wv.x, Aa); Ab = fma2(h0v.y, wv.y, Ab);
            Ba = fma2(h1v.x, wv.x, Ba); Bb = fma2(h1v.y, wv.y, Bb);
        }
        int g0 = 64 * rank + lane, g1 = g0 + 32;
        float abl0 = fsig(f2sum(Aa) + f2sum(Ab) + bab0) * s->qrow[(S - 1) % 3][g0];
        float abl1 = fsig(f2sum(Ba) + f2sum(Bb) + bab0) * s->qrow[(S - 1) % 3][g1];
        float pt = s->discs[1] *
                   ((abl0 - s->diffr[1][g0]) + (abl1 - s->diffr[1][g1]));
#pragma unroll
        for (int off = 16; off; off >>= 1)
            pt += __shfl_xor_sync(0xffffffffu, pt, off);
        if (lane == 0) {
            if (rank == 1) {
                remote_st32(s2u(&s->ypeer[1]), peer, pt);
                remote_arrive(s2u(&s->mb_y[1]), peer);
            } else {
                mbar_wait_acq(s2u(&s->mb_y[1]), (uint32_t)(((S - 2) >> 1) & 1));
                out[b * S + S - 1] = fsig(pt + s->ypeer[1]);
            }
        }
    }
    CLUSTER_SYNC_();   // keep smem alive for in-flight peer ops
}

// -------- launch --------
extern "C" void kernel_launch(void* const* d_in, const int* in_sizes, int n_in,
                              void* d_out, int out_size) {
    const int*   qseq  = (const int*)d_in[0];
    const int*   cseq  = (const int*)d_in[1];
    const float* qmat  = (const float*)d_in[2];
    const float* Eq    = (const float*)d_in[3];
    const float* Ec    = (const float*)d_in[4];
    const float* h0    = (const float*)d_in[5];
    const float* W1    = (const float*)d_in[6];
    const float* b1    = (const float*)d_in[7];
    const float* W2    = (const float*)d_in[8];
    const float* b2    = (const float*)d_in[9];
    const float* W3    = (const float*)d_in[10];
    const float* b3    = (const float*)d_in[11];
    const float* W4    = (const float*)d_in[12];
    const float* b4    = (const float*)d_in[13];
    const float* Wab   = (const float*)d_in[14];
    const float* bab   = (const float*)d_in[15];
    const float* Wdiff = (const float*)d_in[16];
    const float* bdiff = (const float*)d_in[17];
    const float* Wdisc = (const float*)d_in[18];
    const float* bdisc = (const float*)d_in[19];
    float* out = (float*)d_out;

    k_al<<<NQ, 128>>>(Eq, Ec, W1, b1);
    k_dq<<<NQ, 128>>>(Eq, Wdiff, bdiff, Wdisc, bdisc, qmat);
    k_p23<<<B * (S - 1), 128>>>(qseq, cseq, W2, W3, b2, b3);

    cudaFuncSetAttribute(lpkt_main, cudaFuncAttributeMaxDynamicSharedMemorySize,
                         (int)sizeof(Smem));
    lpkt_main<<<2 * B, 512, sizeof(Smem)>>>(qseq, qmat, h0, W2, W3, W4, b4, Wab, bab, out);
}

// round 14
// speedup vs baseline: 1.1402x; 1.1402x over previous
#include <cuda_runtime.h>
#include <cuda_bf16.h>
#include <cstdint>

#define B 64
#define S 128
#define NQ 2000
#define C 128
#define K 64
#define DE 64
#define DC 64
#define HP 68   // padded row stride for h rows in smem (16B-aligned rows)
#define WP 76   // padded row stride for transposed weights

typedef unsigned long long ull;

// -------- scratch (device globals; no allocation allowed) --------
__device__ float d_AL[NQ * 2 * K];
__device__ float d_diffQ[NQ * C];
__device__ float d_discQ[NQ];
__device__ float d_P2[B * (S - 1) * K];
__device__ float d_P3[B * (S - 1) * K];

__device__ __forceinline__ float fsig(float x) {
    return __fdividef(1.0f, 1.0f + __expf(-x));
}
__device__ __forceinline__ ull fma2(ull a, ull b, ull c) {
    ull d;
    asm("fma.rn.f32x2 %0,%1,%2,%3;" : "=l"(d) : "l"(a), "l"(b), "l"(c));
    return d;
}
__device__ __forceinline__ float f2sum(ull v) {
    float lo, hi;
    asm("mov.b64 {%0,%1},%2;" : "=f"(lo), "=f"(hi) : "l"(v));
    return lo + hi;
}
__device__ __forceinline__ ull packf2(float lo, float hi) {
    ull v;
    asm("mov.b64 %0,{%1,%2};" : "=l"(v) : "f"(lo), "f"(hi));
    return v;
}
__device__ __forceinline__ uint32_t s2u(const void* p) {
    uint32_t a;
    asm("{ .reg .u64 t; cvta.to.shared.u64 t, %1; cvt.u32.u64 %0, t; }" : "=r"(a) : "l"(p));
    return a;
}
__device__ __forceinline__ uint32_t ctarank() {
    uint32_t r;
    asm("mov.u32 %0, %%cluster_ctarank;" : "=r"(r));
    return r;
}
__device__ __forceinline__ void mbar_init(uint32_t a, uint32_t cnt) {
    asm volatile("mbarrier.init.shared.b64 [%0], %1;" :: "r"(a), "r"(cnt) : "memory");
}
__device__ __forceinline__ void mbar_wait_acq(uint32_t a, uint32_t par) {
    asm volatile(
        "{\n\t.reg .pred P;\n\t"
        "WL_%=:\n\t"
        "mbarrier.try_wait.parity.acquire.cluster.shared::cta.b64 P, [%0], %1, 0x989680;\n\t"
        "@!P bra WL_%=;\n\t}"
        :: "r"(a), "r"(par) : "memory");
}
__device__ __forceinline__ void remote_st64(uint32_t a, uint32_t rank, ull v) {
    asm volatile(
        "{\n\t.reg .b32 r;\n\t"
        "mapa.shared::cluster.u32 r, %0, %1;\n\t"
        "st.shared::cluster.b64 [r], %2;\n\t}"
        :: "r"(a), "r"(rank), "l"(v) : "memory");
}
__device__ __forceinline__ void remote_st32(uint32_t a, uint32_t rank, float v) {
    asm volatile(
        "{\n\t.reg .b32 r;\n\t"
        "mapa.shared::cluster.u32 r, %0, %1;\n\t"
        "st.shared::cluster.b32 [r], %2;\n\t}"
        :: "r"(a), "r"(rank), "f"(v) : "memory");
}
__device__ __forceinline__ void remote_arrive(uint32_t a, uint32_t rank) {
    asm volatile(
        "{\n\t.reg .b32 r;\n\t"
        "mapa.shared::cluster.u32 r, %0, %1;\n\t"
        "mbarrier.arrive.release.cluster.shared::cluster.b64 _, [r];\n\t}"
        :: "r"(a), "r"(rank) : "memory");
}
#define CLUSTER_SYNC_() do { \
    asm volatile("barrier.cluster.arrive.aligned;" ::: "memory"); \
    asm volatile("barrier.cluster.wait.aligned;" ::: "memory"); \
} while (0)

// -------- precompute kernels --------
__global__ void k_al(const float* __restrict__ Eq, const float* __restrict__ Ec,
                     const float* __restrict__ W1, const float* __restrict__ b1) {
    int q = blockIdx.x;
    int tid = threadIdx.x;
    __shared__ float eq[DE];
    if (tid < DE) eq[tid] = Eq[q * DE + tid];
    __syncthreads();
    int corr = tid >> 6;
    int k = tid & 63;
    float a = b1[k];
#pragma unroll 4
    for (int d = 0; d < DE; d++) a = fmaf(eq[d], W1[d * K + k], a);
#pragma unroll 4
    for (int d = 0; d < DC; d++) a = fmaf(Ec[corr * DC + d], W1[(DE + d) * K + k], a);
    d_AL[(q * 2 + corr) * K + k] = a;
}

__global__ void k_dq(const float* __restrict__ Eq, const float* __restrict__ Wdiff,
                     const float* __restrict__ bdiff, const float* __restrict__ Wdisc,
                     const float* __restrict__ bdisc, const float* __restrict__ qmat) {
    int q = blockIdx.x;
    int c = threadIdx.x;
    __shared__ float eq[DE];
    if (c < DE) eq[c] = Eq[q * DE + c];
    __syncthreads();
    float a = bdiff[c];
#pragma unroll 4
    for (int d = 0; d < DE; d++) a = fmaf(eq[d], Wdiff[d * C + c], a);
    d_diffQ[q * C + c] = fsig(a) * qmat[q * C + c];
    if (c == 0) {
        float dd = bdisc[0];
        for (int d = 0; d < DE; d++) dd = fmaf(eq[d], Wdisc[d], dd);
        d_discQ[q] = fsig(dd) * 5.0f;
    }
}

__global__ void k_p23(const int* __restrict__ qseq, const int* __restrict__ cseq,
                      const float* __restrict__ W2, const float* __restrict__ W3,
                      const float* __restrict__ b2, const float* __restrict__ b3) {
    int blk = blockIdx.x;
    int b = blk / (S - 1);
    int t = blk % (S - 1);
    __shared__ float lp[K], lc[K];
    int tid = threadIdx.x;
    if (tid < K) {
        int qc = qseq[b * S + t], cc = cseq[b * S + t];
        lc[tid] = d_AL[(qc * 2 + cc) * K + tid];
        if (t > 0) {
            int qp = qseq[b * S + t - 1], cp = cseq[b * S + t - 1];
            lp[tid] = d_AL[(qp * 2 + cp) * K + tid];
        } else {
            lp[tid] = 0.0f;
        }
    }
    __syncthreads();
    int which = tid >> 6;
    int k = tid & 63;
    const float* W = which ? W3 : W2;
    float a = which ? b3[k] : b2[k];
#pragma unroll 4
    for (int j = 0; j < K; j++) a = fmaf(lp[j], W[j * K + k], a);
#pragma unroll 4
    for (int j = 0; j < K; j++) a = fmaf(lc[j], W[(K + j) * K + k], a);
    float* dst = which ? d_P3 : d_P2;
    dst[blk * K + k] = a;
}

// -------- main kernel: cluster of 2 CTAs per batch (c-split), 512 threads --------
// ALL warps matmul with COMPILE-TIME row counts: pair0 (P1) 4 rows,
// pair1 (y+prefetch) 6 rows, pairs 2-7 9 rows each. 4+6+54 = 64.
struct __align__(16) Smem {
    float W4bT[K * WP];      // [k][j]
    float W2hT[K * WP];      // [k][j]
    float W3hT[K * WP];      // [k][j]
    float hs[2][64 * HP];    // own 64 c-rows, double buffered
    float part[8][K];        // per-pair h_tilde partials (local)
    float htld[K];           // combined own+peer h_tilde (for P1 dot)
    float htpeer[2][K];      // peer's h_tilde partial (slot = step parity)
    float LGs[K];
    float lgt[K];
    float qrow[3][C];
    float diffr[2][C];
    float Wabs[K];
    float b4s[K];
    float discs[2];
    float ypeer[2];
    ull mb_ht[2];
    ull mb_y[2];
};

template <int CNT>
__device__ __forceinline__ void mm_rows(const float* __restrict__ hcur, int r0,
                                        const ull* __restrict__ wreg, ull* acc) {
#pragma unroll
    for (int r = 0; r < CNT; r++) acc[r] = 0ull;
#pragma unroll
    for (int q = 0; q < 16; q++) {
#pragma unroll
        for (int r = 0; r < CNT; r++) {
            ulonglong2 hv = *(const ulonglong2*)(hcur + (r0 + r) * HP + 4 * q);
            acc[r] = fma2(hv.x, wreg[2 * q], acc[r]);
            acc[r] = fma2(hv.y, wreg[2 * q + 1], acc[r]);
        }
    }
}

template <int CNT>
__device__ __forceinline__ float epi_rows(Smem* s, const float* __restrict__ hcur,
                                          float* __restrict__ hnew, int r0, int kk,
                                          int rankoff, int t3, int t3n, const ull* acc) {
    float LGk = s->LGs[kk];
    float lgtk = s->lgt[kk];
    float htn = 0.0f;
#pragma unroll
    for (int r = 0; r < CNT; r++) {
        int c = r0 + r;
        int gc = rankoff + c;
        float qev = s->qrow[t3][gc];
        float qnv = s->qrow[t3n][gc];
        float ho = hcur[c * HP + kk];
        float a = f2sum(acc[r]) + lgtk;
        float gf = fsig(a);
        float v = fmaf(qev, LGk, gf * ho);
        hnew[c * HP + kk] = v;
        htn = fmaf(qnv, v, htn);
    }
    return htn;
}

__global__ void __launch_bounds__(512, 1) __cluster_dims__(2, 1, 1)
lpkt_main(const int* __restrict__ qseq, const float* __restrict__ qmat,
          const float* __restrict__ h0,
          const float* __restrict__ W2, const float* __restrict__ W3,
          const float* __restrict__ W4, const float* __restrict__ b4,
          const float* __restrict__ Wab, const float* __restrict__ bab,
          float* __restrict__ out) {
    extern __shared__ char raw[];
    Smem* s = (Smem*)raw;
    const int b = blockIdx.x >> 1;
    const uint32_t rank = ctarank();
    const uint32_t peer = rank ^ 1u;
    const int tid = threadIdx.x;
    const int lane = tid & 31;
    const int wid = tid >> 5;                 // 0..15
    const int kk = 32 * (wid & 1) + lane;     // owned k column
    const int pr = wid >> 1;                  // pair index 0..7
    const int r0 = (pr == 0) ? 0 : (pr == 1) ? 4 : 10 + 9 * (pr - 2);
    const int rankoff = 64 * (int)rank;
    const float bab0 = __ldg(bab);

    // ---- W4 top block column -> registers (loop-invariant, reused 127 steps) ----
    ull wreg[32];
#pragma unroll
    for (int q = 0; q < 32; q++)
        wreg[q] = packf2(W4[(2 * q) * K + kk], W4[(2 * q + 1) * K + kk]);

    // ---- init smem ----
    for (int i = tid; i < K * K; i += 512) {
        int j = i & 63, k = i >> 6;
        s->W4bT[k * WP + j] = W4[(K + j) * K + k];
        s->W2hT[k * WP + j] = W2[(128 + j) * K + k];
        s->W3hT[k * WP + j] = W3[(128 + j) * K + k];
    }
    for (int i = tid; i < 64 * K; i += 512) {
        int c = i >> 6, k = i & 63;
        s->hs[0][c * HP + k] = h0[(rankoff + c) * K + k];
    }
    if (tid < K) { s->Wabs[tid] = Wab[tid]; s->b4s[tid] = b4[tid]; }
    if (tid < C) {
        int q0 = qseq[b * S + 0], q1 = qseq[b * S + 1];
        s->qrow[0][tid] = qmat[q0 * C + tid];
        s->qrow[1][tid] = qmat[q1 * C + tid];
    }
    if (tid == 0) {
        if (rank == 0) out[b * S] = 0.0f;
        mbar_init(s2u(&s->mb_ht[0]), 16);
        mbar_init(s2u(&s->mb_ht[1]), 16);
        mbar_init(s2u(&s->mb_y[0]), 1);
        mbar_init(s2u(&s->mb_y[1]), 1);
    }
    float a2pre = 0.0f, a3pre = 0.0f;
    if (tid < K) {
        a2pre = d_P2[(b * (S - 1)) * K + tid];
        a3pre = d_P3[(b * (S - 1)) * K + tid];
    }
    __syncthreads();
    // h_tilde0 own partial -> part[0]; part[1..7] = 0
    if (tid < K) {
        float acc0 = 0.0f, acc1 = 0.0f;
        for (int c = 0; c < 64; c += 2) {
            acc0 = fmaf(s->qrow[0][rankoff + c], s->hs[0][c * HP + tid], acc0);
            acc1 = fmaf(s->qrow[0][rankoff + c + 1], s->hs[0][(c + 1) * HP + tid], acc1);
        }
        s->part[0][tid] = acc0 + acc1;
#pragma unroll
        for (int gg = 1; gg < 8; gg++) s->part[gg][tid] = 0.0f;
    }
    __syncthreads();
    CLUSTER_SYNC_();   // mbarriers initialized in both CTAs; part[] visible
    // initial send: h_tilde0 partial -> peer slot 0
    if (wid == 13 && lane < 16) {
        int base = lane * 4;
        float4 p = *(const float4*)&s->part[0][base];
        uint32_t dst = s2u(&s->htpeer[0][base]);
        remote_st64(dst, peer, packf2(p.x, p.y));
        remote_st64(dst + 8, peer, packf2(p.z, p.w));
        remote_arrive(s2u(&s->mb_ht[0]), peer);
    }

    float ypprev = 0.0f;

    for (int t = 0; t < S - 1; t++) {
        const int t3 = t % 3;
        const int t3n = (t + 1) % 3;
        const int cb = t & 1;
        const int nb = cb ^ 1;
        const float* __restrict__ hcur = s->hs[cb];
        float* __restrict__ hnew = s->hs[nb];

        ull acc[9];

        // ---- side phases, then EVERY warp runs its (small) matmul slice ----
        if (tid < 64) {
            // ==== P1: wait peer, combined reduce, single dot, lgt ====
            const int k = tid;
            mbar_wait_acq(s2u(&s->mb_ht[cb]), (uint32_t)((t >> 1) & 1));
            float hsum = s->htpeer[cb][k];
#pragma unroll
            for (int gg = 0; gg < 8; gg++) hsum += s->part[gg][k];
            s->htld[k] = hsum;
            asm volatile("bar.sync 1, 64;" ::: "memory");
            ull A2a = 0, A2b = 0, A3a = 0, A3b = 0;
            const float* w2p = s->W2hT + k * WP;
            const float* w3p = s->W3hT + k * WP;
#pragma unroll
            for (int q = 0; q < 16; q++) {
                ulonglong2 hp = *(const ulonglong2*)(s->htld + 4 * q);
                ulonglong2 w2v = *(const ulonglong2*)(w2p + 4 * q);
                ulonglong2 w3v = *(const ulonglong2*)(w3p + 4 * q);
                A2a = fma2(hp.x, w2v.x, A2a); A2b = fma2(hp.y, w2v.y, A2b);
                A3a = fma2(hp.x, w3v.x, A3a); A3b = fma2(hp.y, w3v.y, A3b);
            }
            float a2 = a2pre + f2sum(A2a) + f2sum(A2b);
            float a3 = a3pre + f2sum(A3a) + f2sum(A3b);
            s->LGs[k] = fsig(a3) * fsig(2.0f * a2);   // (tanh+1)/2 == sigmoid(2x)
            asm volatile("bar.sync 1, 64;" ::: "memory");
            // lgt = b4 + LG @ W4b
            ull La = 0, Lb = 0;
            const float* wbp = s->W4bT + k * WP;
#pragma unroll
            for (int q = 0; q < 16; q++) {
                ulonglong2 lg = *(const ulonglong2*)(s->LGs + 4 * q);
                ulonglong2 w = *(const ulonglong2*)(wbp + 4 * q);
                La = fma2(lg.x, w.x, La); Lb = fma2(lg.y, w.y, Lb);
            }
            s->lgt[k] = s->b4s[k] + f2sum(La) + f2sum(Lb);
            if (t + 1 < S - 1) {
                a2pre = d_P2[(b * (S - 1) + t + 1) * K + tid];
                a3pre = d_P3[(b * (S - 1) + t + 1) * K + tid];
            }
            mm_rows<4>(hcur, r0, wreg, acc);
        } else if (wid == 2) {
            // ==== y_t partial over own 64 rows; rank0 flushes out[t-1] ====
            float pt = 0.0f;
            if (t > 0) {
                ull Aa = 0, Ab = 0, Ba = 0, Bb = 0;
                const float* rr0 = hcur + lane * HP;
                const float* rr1 = hcur + (lane + 32) * HP;
#pragma unroll
                for (int q = 0; q < 16; q++) {
                    ulonglong2 wv = *(const ulonglong2*)(s->Wabs + 4 * q);
                    ulonglong2 h0v = *(const ulonglong2*)(rr0 + 4 * q);
                    ulonglong2 h1v = *(const ulonglong2*)(rr1 + 4 * q);
                    Aa = fma2(h0v.x, wv.x, Aa); Ab = fma2(h0v.y, wv.y, Ab);
                    Ba = fma2(h1v.x, wv.x, Ba); Bb = fma2(h1v.y, wv.y, Bb);
                }
                int g0 = rankoff + lane, g1 = g0 + 32;
                float abl0 = fsig(f2sum(Aa) + f2sum(Ab) + bab0) * s->qrow[t3][g0];
                float abl1 = fsig(f2sum(Ba) + f2sum(Bb) + bab0) * s->qrow[t3][g1];
                pt = s->discs[cb] *
                     ((abl0 - s->diffr[cb][g0]) + (abl1 - s->diffr[cb][g1]));
#pragma unroll
                for (int off = 16; off; off >>= 1)
                    pt += __shfl_xor_sync(0xffffffffu, pt, off);
            }
            if (rank == 1) {
                if (t > 0 && lane == 0) {
                    remote_st32(s2u(&s->ypeer[cb]), peer, pt);
                    remote_arrive(s2u(&s->mb_y[cb]), peer);
                }
            } else {
                if (t > 1 && lane == 0) {
                    int pb = (t - 1) & 1;
                    mbar_wait_acq(s2u(&s->mb_y[pb]), (uint32_t)(((t - 2) >> 1) & 1));
                    out[b * S + t - 1] = fsig(ypprev + s->ypeer[pb]);
                }
                ypprev = pt;
            }
            mm_rows<6>(hcur, r0, wreg, acc);
        } else if (wid == 3) {
            // ==== prefetch next q rows / diff / disc ====
            int t2 = (t + 2 < S) ? (t + 2) : (S - 1);
            int q2v = qseq[b * S + t2];
            int q1v = qseq[b * S + t + 1];
#pragma unroll
            for (int h = 0; h < 2; h++) {
                int i2 = lane + 32 * h;
                *(float2*)(s->qrow[(t + 2) % 3] + 2 * i2) =
                    *(const float2*)(qmat + q2v * C + 2 * i2);
                *(float2*)(s->diffr[nb] + 2 * i2) =
                    *(const float2*)(d_diffQ + q1v * C + 2 * i2);
            }
            if (lane == 0) s->discs[nb] = d_discQ[q1v];
            mm_rows<6>(hcur, r0, wreg, acc);
        } else {
            mm_rows<9>(hcur, r0, wreg, acc);
        }
        __syncthreads();   // sync1: LGs/lgt ready, prefetch done

        // ==== epilogue (templated per pair) ====
        float htn;
        if (pr == 0)      htn = epi_rows<4>(s, hcur, hnew, r0, kk, rankoff, t3, t3n, acc);
        else if (pr == 1) htn = epi_rows<6>(s, hcur, hnew, r0, kk, rankoff, t3, t3n, acc);
        else              htn = epi_rows<9>(s, hcur, hnew, r0, kk, rankoff, t3, t3n, acc);
        s->part[pr][kk] = htn;
        __syncthreads();   // sync2: hnew + part complete

        // ---- send summed h_tilde partial for step t+1 to peer ----
        if (wid == 13 && lane < 16 && t < S - 2) {
            int base = lane * 4;
            float4 p = *(const float4*)&s->part[0][base];
#pragma unroll
            for (int gg = 1; gg < 8; gg++) {
                float4 t4 = *(const float4*)&s->part[gg][base];
                p.x += t4.x; p.y += t4.y; p.z += t4.z; p.w += t4.w;
            }
            uint32_t dst = s2u(&s->htpeer[nb][base]);
            remote_st64(dst, peer, packf2(p.x, p.y));
            remote_st64(dst + 8, peer, packf2(p.z, p.w));
            remote_arrive(s2u(&s->mb_ht[nb]), peer);
        }
    }

    // ==== tail ====
    if (wid == 2) {
        // flush out[S-2] on rank0
        if (rank == 0 && lane == 0) {
            int pb = (S - 2) & 1;   // 0
            mbar_wait_acq(s2u(&s->mb_y[pb]), (uint32_t)(((S - 3) >> 1) & 1));
            out[b * S + (S - 2)] = fsig(ypprev + s->ypeer[pb]);
        }
        // final y_{S-1} on h state hs[1]
        const float* hfin = s->hs[(S - 1) & 1];
        ull Aa = 0, Ab = 0, Ba = 0, Bb = 0;
        const float* rr0 = hfin + lane * HP;
        const float* rr1 = hfin + (lane + 32) * HP;
#pragma unroll
        for (int q = 0; q < 16; q++) {
            ulonglong2 wv = *(const ulonglong2*)(s->Wabs + 4 * q);
            ulonglong2 h0v = *(const ulonglong2*)(rr0 + 4 * q);
            ulonglong2 h1v = *(const ulonglong2*)(rr1 + 4 * q);
            Aa = fma2(h0v.x, wv.x, Aa); Ab = fma2(h0v.y, wv.y, Ab);
            Ba = fma2(h1v.x, wv.x, Ba); Bb = fma2(h1v.y, wv.y, Bb);
        }
        int g0 = rankoff + lane, g1 = g0 + 32;
        float abl0 = fsig(f2sum(Aa) + f2sum(Ab) + bab0) * s->qrow[(S - 1) % 3][g0];
        float abl1 = fsig(f2sum(Ba) + f2sum(Bb) + bab0) * s->qrow[(S - 1) % 3][g1];
        float pt = s->discs[1] *
                   ((abl0 - s->diffr[1][g0]) + (abl1 - s->diffr[1][g1]));
#pragma unroll
        for (int off = 16; off; off >>= 1)
            pt += __shfl_xor_sync(0xffffffffu, pt, off);
        if (lane == 0) {
            if (rank == 1) {
                remote_st32(s2u(&s->ypeer[1]), peer, pt);
                remote_arrive(s2u(&s->mb_y[1]), peer);
            } else {
                mbar_wait_acq(s2u(&s->mb_y[1]), (uint32_t)(((S - 2) >> 1) & 1));
                out[b * S + S - 1] = fsig(pt + s->ypeer[1]);
            }
        }
    }
    CLUSTER_SYNC_();   // keep smem alive for in-flight peer ops
}

// -------- launch --------
extern "C" void kernel_launch(void* const* d_in, const int* in_sizes, int n_in,
                              void* d_out, int out_size) {
    const int*   qseq  = (const int*)d_in[0];
    const int*   cseq  = (const int*)d_in[1];
    const float* qmat  = (const float*)d_in[2];
    const float* Eq    = (const float*)d_in[3];
    const float* Ec    = (const float*)d_in[4];
    const float* h0    = (const float*)d_in[5];
    const float* W1    = (const float*)d_in[6];
    const float* b1    = (const float*)d_in[7];
    const float* W2    = (const float*)d_in[8];
    const float* b2    = (const float*)d_in[9];
    const float* W3    = (const float*)d_in[10];
    const float* b3    = (const float*)d_in[11];
    const float* W4    = (const float*)d_in[12];
    const float* b4    = (const float*)d_in[13];
    const float* Wab   = (const float*)d_in[14];
    const float* bab   = (const float*)d_in[15];
    const float* Wdiff = (const float*)d_in[16];
    const float* bdiff = (const float*)d_in[17];
    const float* Wdisc = (const float*)d_in[18];
    const float* bdisc = (const float*)d_in[19];
    float* out = (float*)d_out;

    k_al<<<NQ, 128>>>(Eq, Ec, W1, b1);
    k_dq<<<NQ, 128>>>(Eq, Wdiff, bdiff, Wdisc, bdisc, qmat);
    k_p23<<<B * (S - 1), 128>>>(qseq, cseq, W2, W3, b2, b3);

    cudaFuncSetAttribute(lpkt_main, cudaFuncAttributeMaxDynamicSharedMemorySize,
                         (int)sizeof(Smem));
    lpkt_main<<<2 * B, 512, sizeof(Smem)>>>(qseq, qmat, h0, W2, W3, W4, b4, Wab, bab, out);
}

// round 15
// speedup vs baseline: 1.1802x; 1.0351x over previous
#include <cuda_runtime.h>
#include <cuda_bf16.h>
#include <cstdint>

#define B 64
#define S 128
#define NQ 2000
#define C 128
#define K 64
#define DE 64
#define DC 64
#define HP 68   // padded row stride for h rows in smem (16B-aligned rows)
#define WP 76   // padded row stride for transposed weights

typedef unsigned long long ull;

// -------- scratch (device globals; no allocation allowed) --------
__device__ float d_AL[NQ * 2 * K];
__device__ float d_diffQ[NQ * C];
__device__ float d_discQ[NQ];
__device__ float d_P2[B * (S - 1) * K];
__device__ float d_P3[B * (S - 1) * K];

__device__ __forceinline__ float fsig(float x) {
    return __fdividef(1.0f, 1.0f + __expf(-x));
}
__device__ __forceinline__ ull fma2(ull a, ull b, ull c) {
    ull d;
    asm("fma.rn.f32x2 %0,%1,%2,%3;" : "=l"(d) : "l"(a), "l"(b), "l"(c));
    return d;
}
__device__ __forceinline__ float f2sum(ull v) {
    float lo, hi;
    asm("mov.b64 {%0,%1},%2;" : "=f"(lo), "=f"(hi) : "l"(v));
    return lo + hi;
}
__device__ __forceinline__ ull packf2(float lo, float hi) {
    ull v;
    asm("mov.b64 %0,{%1,%2};" : "=l"(v) : "f"(lo), "f"(hi));
    return v;
}
__device__ __forceinline__ uint32_t s2u(const void* p) {
    uint32_t a;
    asm("{ .reg .u64 t; cvta.to.shared.u64 t, %1; cvt.u32.u64 %0, t; }" : "=r"(a) : "l"(p));
    return a;
}
__device__ __forceinline__ uint32_t ctarank() {
    uint32_t r;
    asm("mov.u32 %0, %%cluster_ctarank;" : "=r"(r));
    return r;
}
__device__ __forceinline__ void mbar_init(uint32_t a, uint32_t cnt) {
    asm volatile("mbarrier.init.shared.b64 [%0], %1;" :: "r"(a), "r"(cnt) : "memory");
}
__device__ __forceinline__ void mbar_wait_acq(uint32_t a, uint32_t par) {
    asm volatile(
        "{\n\t.reg .pred P;\n\t"
        "WL_%=:\n\t"
        "mbarrier.try_wait.parity.acquire.cluster.shared::cta.b64 P, [%0], %1, 0x989680;\n\t"
        "@!P bra WL_%=;\n\t}"
        :: "r"(a), "r"(par) : "memory");
}
__device__ __forceinline__ void remote_st64(uint32_t a, uint32_t rank, ull v) {
    asm volatile(
        "{\n\t.reg .b32 r;\n\t"
        "mapa.shared::cluster.u32 r, %0, %1;\n\t"
        "st.shared::cluster.b64 [r], %2;\n\t}"
        :: "r"(a), "r"(rank), "l"(v) : "memory");
}
__device__ __forceinline__ void remote_st32(uint32_t a, uint32_t rank, float v) {
    asm volatile(
        "{\n\t.reg .b32 r;\n\t"
        "mapa.shared::cluster.u32 r, %0, %1;\n\t"
        "st.shared::cluster.b32 [r], %2;\n\t}"
        :: "r"(a), "r"(rank), "f"(v) : "memory");
}
__device__ __forceinline__ void remote_arrive(uint32_t a, uint32_t rank) {
    asm volatile(
        "{\n\t.reg .b32 r;\n\t"
        "mapa.shared::cluster.u32 r, %0, %1;\n\t"
        "mbarrier.arrive.release.cluster.shared::cluster.b64 _, [r];\n\t}"
        :: "r"(a), "r"(rank) : "memory");
}
#define CLUSTER_SYNC_() do { \
    asm volatile("barrier.cluster.arrive.aligned;" ::: "memory"); \
    asm volatile("barrier.cluster.wait.aligned;" ::: "memory"); \
} while (0)

// -------- precompute kernels --------
__global__ void k_al(const float* __restrict__ Eq, const float* __restrict__ Ec,
                     const float* __restrict__ W1, const float* __restrict__ b1) {
    int q = blockIdx.x;
    int tid = threadIdx.x;
    __shared__ float eq[DE];
    if (tid < DE) eq[tid] = Eq[q * DE + tid];
    __syncthreads();
    int corr = tid >> 6;
    int k = tid & 63;
    float a = b1[k];
#pragma unroll 4
    for (int d = 0; d < DE; d++) a = fmaf(eq[d], W1[d * K + k], a);
#pragma unroll 4
    for (int d = 0; d < DC; d++) a = fmaf(Ec[corr * DC + d], W1[(DE + d) * K + k], a);
    d_AL[(q * 2 + corr) * K + k] = a;
}

__global__ void k_dq(const float* __restrict__ Eq, const float* __restrict__ Wdiff,
                     const float* __restrict__ bdiff, const float* __restrict__ Wdisc,
                     const float* __restrict__ bdisc, const float* __restrict__ qmat) {
    int q = blockIdx.x;
    int c = threadIdx.x;
    __shared__ float eq[DE];
    if (c < DE) eq[c] = Eq[q * DE + c];
    __syncthreads();
    float a = bdiff[c];
#pragma unroll 4
    for (int d = 0; d < DE; d++) a = fmaf(eq[d], Wdiff[d * C + c], a);
    d_diffQ[q * C + c] = fsig(a) * qmat[q * C + c];
    if (c == 0) {
        float dd = bdisc[0];
        for (int d = 0; d < DE; d++) dd = fmaf(eq[d], Wdisc[d], dd);
        d_discQ[q] = fsig(dd) * 5.0f;
    }
}

__global__ void k_p23(const int* __restrict__ qseq, const int* __restrict__ cseq,
                      const float* __restrict__ W2, const float* __restrict__ W3,
                      const float* __restrict__ b2, const float* __restrict__ b3) {
    int blk = blockIdx.x;
    int b = blk / (S - 1);
    int t = blk % (S - 1);
    __shared__ float lp[K], lc[K];
    int tid = threadIdx.x;
    if (tid < K) {
        int qc = qseq[b * S + t], cc = cseq[b * S + t];
        lc[tid] = d_AL[(qc * 2 + cc) * K + tid];
        if (t > 0) {
            int qp = qseq[b * S + t - 1], cp = cseq[b * S + t - 1];
            lp[tid] = d_AL[(qp * 2 + cp) * K + tid];
        } else {
            lp[tid] = 0.0f;
        }
    }
    __syncthreads();
    int which = tid >> 6;
    int k = tid & 63;
    const float* W = which ? W3 : W2;
    float a = which ? b3[k] : b2[k];
#pragma unroll 4
    for (int j = 0; j < K; j++) a = fmaf(lp[j], W[j * K + k], a);
#pragma unroll 4
    for (int j = 0; j < K; j++) a = fmaf(lc[j], W[(K + j) * K + k], a);
    float* dst = which ? d_P3 : d_P2;
    dst[blk * K + k] = a;
}

// -------- main kernel: cluster of 2 CTAs per batch (c-split), 512 threads --------
// q-split matmul: warp pair g covers its row group for ALL 64 k (2 k per lane);
// even warp = q-low half + epilogue, odd warp = q-high half (stores partials).
// Row groups: {4,6,9,9,9,9,9,9} = 64.  P1=warps0-1, y=2, prefetch=3, send=13.
struct __align__(16) Smem {
    float W4bT[K * WP];      // [k][j]
    float W2hT[K * WP];      // [k][j]
    float W3hT[K * WP];      // [k][j]
    float hs[2][64 * HP];    // own 64 c-rows, double buffered
    float qpart[64][K];      // q-high partial sums (row x k)
    float part[8][K];        // per-group h_tilde partials (local)
    float htld[K];           // combined own+peer h_tilde (for P1 dot)
    float htpeer[2][K];      // peer's h_tilde partial (slot = step parity)
    float LGs[K];
    float lgt[K];
    float qrow[3][C];
    float diffr[2][C];
    float Wabs[K];
    float b4s[K];
    float discs[2];
    float ypeer[2];
    ull mb_ht[2];
    ull mb_y[2];
};

// matmul over q-half: CNT rows, 2 k columns per lane; odd warps store partials
template <int CNT>
__device__ __forceinline__ void mm_q(Smem* s, const float* __restrict__ hcur, int r0,
                                     int qoff, const ull* __restrict__ wreg,
                                     ull (*acc)[2], bool odd, int lane) {
#pragma unroll
    for (int r = 0; r < CNT; r++) { acc[r][0] = 0ull; acc[r][1] = 0ull; }
#pragma unroll
    for (int qc = 0; qc < 8; qc++) {
#pragma unroll
        for (int r = 0; r < CNT; r++) {
            ulonglong2 hv = *(const ulonglong2*)(hcur + (r0 + r) * HP + qoff + 4 * qc);
            acc[r][0] = fma2(hv.x, wreg[2 * qc], acc[r][0]);
            acc[r][0] = fma2(hv.y, wreg[2 * qc + 1], acc[r][0]);
            acc[r][1] = fma2(hv.x, wreg[16 + 2 * qc], acc[r][1]);
            acc[r][1] = fma2(hv.y, wreg[16 + 2 * qc + 1], acc[r][1]);
        }
    }
    if (odd) {
#pragma unroll
        for (int r = 0; r < CNT; r++) {
            s->qpart[r0 + r][lane] = f2sum(acc[r][0]);
            s->qpart[r0 + r][lane + 32] = f2sum(acc[r][1]);
        }
    }
}

// epilogue on even warps: combine own (q-low) + qpart (q-high), gate, update h
template <int CNT>
__device__ __forceinline__ void epi_q(Smem* s, const float* __restrict__ hcur,
                                      float* __restrict__ hnew, int r0, int lane,
                                      int pr, int rankoff, int t3, int t3n,
                                      const ull (*acc)[2]) {
    float LG0 = s->LGs[lane], LG1 = s->LGs[lane + 32];
    float lg0 = s->lgt[lane], lg1 = s->lgt[lane + 32];
    float htn0 = 0.0f, htn1 = 0.0f;
#pragma unroll
    for (int r = 0; r < CNT; r++) {
        int c = r0 + r;
        int gc = rankoff + c;
        float qev = s->qrow[t3][gc];
        float qnv = s->qrow[t3n][gc];
        float a0 = f2sum(acc[r][0]) + s->qpart[c][lane] + lg0;
        float a1 = f2sum(acc[r][1]) + s->qpart[c][lane + 32] + lg1;
        float gf0 = fsig(a0);
        float gf1 = fsig(a1);
        float ho0 = hcur[c * HP + lane];
        float ho1 = hcur[c * HP + lane + 32];
        float v0 = fmaf(qev, LG0, gf0 * ho0);
        float v1 = fmaf(qev, LG1, gf1 * ho1);
        hnew[c * HP + lane] = v0;
        hnew[c * HP + lane + 32] = v1;
        htn0 = fmaf(qnv, v0, htn0);
        htn1 = fmaf(qnv, v1, htn1);
    }
    s->part[pr][lane] = htn0;
    s->part[pr][lane + 32] = htn1;
}

__global__ void __launch_bounds__(512, 1) __cluster_dims__(2, 1, 1)
lpkt_main(const int* __restrict__ qseq, const float* __restrict__ qmat,
          const float* __restrict__ h0,
          const float* __restrict__ W2, const float* __restrict__ W3,
          const float* __restrict__ W4, const float* __restrict__ b4,
          const float* __restrict__ Wab, const float* __restrict__ bab,
          float* __restrict__ out) {
    extern __shared__ char raw[];
    Smem* s = (Smem*)raw;
    const int b = blockIdx.x >> 1;
    const uint32_t rank = ctarank();
    const uint32_t peer = rank ^ 1u;
    const int tid = threadIdx.x;
    const int lane = tid & 31;
    const int wid = tid >> 5;                 // 0..15
    const int pr = wid >> 1;                  // group index 0..7
    const bool odd = (wid & 1) != 0;          // q-high warp
    const int qoff = odd ? 32 : 0;
    const int r0 = (pr == 0) ? 0 : (pr == 1) ? 4 : 10 + 9 * (pr - 2);
    const int rankoff = 64 * (int)rank;
    const float bab0 = __ldg(bab);

    // ---- W4 top block, 2 k columns per lane for this warp's q-half ----
    ull wreg[32];
#pragma unroll
    for (int i = 0; i < 16; i++) {
        wreg[i] = packf2(W4[(qoff + 2 * i) * K + lane], W4[(qoff + 2 * i + 1) * K + lane]);
        wreg[16 + i] = packf2(W4[(qoff + 2 * i) * K + lane + 32],
                              W4[(qoff + 2 * i + 1) * K + lane + 32]);
    }

    // ---- init smem ----
    for (int i = tid; i < K * K; i += 512) {
        int j = i & 63, k = i >> 6;
        s->W4bT[k * WP + j] = W4[(K + j) * K + k];
        s->W2hT[k * WP + j] = W2[(128 + j) * K + k];
        s->W3hT[k * WP + j] = W3[(128 + j) * K + k];
    }
    for (int i = tid; i < 64 * K; i += 512) {
        int c = i >> 6, k = i & 63;
        s->hs[0][c * HP + k] = h0[(rankoff + c) * K + k];
    }
    if (tid < K) { s->Wabs[tid] = Wab[tid]; s->b4s[tid] = b4[tid]; }
    if (tid < C) {
        int q0 = qseq[b * S + 0], q1 = qseq[b * S + 1];
        s->qrow[0][tid] = qmat[q0 * C + tid];
        s->qrow[1][tid] = qmat[q1 * C + tid];
    }
    if (tid == 0) {
        if (rank == 0) out[b * S] = 0.0f;
        mbar_init(s2u(&s->mb_ht[0]), 16);
        mbar_init(s2u(&s->mb_ht[1]), 16);
        mbar_init(s2u(&s->mb_y[0]), 1);
        mbar_init(s2u(&s->mb_y[1]), 1);
    }
    float a2pre = 0.0f, a3pre = 0.0f;
    if (tid < K) {
        a2pre = d_P2[(b * (S - 1)) * K + tid];
        a3pre = d_P3[(b * (S - 1)) * K + tid];
    }
    __syncthreads();
    // h_tilde0 own partial -> part[0]; part[1..7] = 0
    if (tid < K) {
        float acc0 = 0.0f, acc1 = 0.0f;
        for (int c = 0; c < 64; c += 2) {
            acc0 = fmaf(s->qrow[0][rankoff + c], s->hs[0][c * HP + tid], acc0);
            acc1 = fmaf(s->qrow[0][rankoff + c + 1], s->hs[0][(c + 1) * HP + tid], acc1);
        }
        s->part[0][tid] = acc0 + acc1;
#pragma unroll
        for (int gg = 1; gg < 8; gg++) s->part[gg][tid] = 0.0f;
    }
    __syncthreads();
    CLUSTER_SYNC_();   // mbarriers initialized in both CTAs; part[] visible
    // initial send: h_tilde0 partial -> peer slot 0
    if (wid == 13 && lane < 16) {
        int base = lane * 4;
        float4 p = *(const float4*)&s->part[0][base];
        uint32_t dst = s2u(&s->htpeer[0][base]);
        remote_st64(dst, peer, packf2(p.x, p.y));
        remote_st64(dst + 8, peer, packf2(p.z, p.w));
        remote_arrive(s2u(&s->mb_ht[0]), peer);
    }

    float ypprev = 0.0f;

    for (int t = 0; t < S - 1; t++) {
        const int t3 = t % 3;
        const int t3n = (t + 1) % 3;
        const int cb = t & 1;
        const int nb = cb ^ 1;
        const float* __restrict__ hcur = s->hs[cb];
        float* __restrict__ hnew = s->hs[nb];

        ull acc[9][2];

        // ---- side phases, then every warp runs its q-half matmul slice ----
        if (tid < 64) {
            // ==== P1: wait peer, combined reduce, single dot, lgt ====
            const int k = tid;
            mbar_wait_acq(s2u(&s->mb_ht[cb]), (uint32_t)((t >> 1) & 1));
            float hsum = s->htpeer[cb][k];
#pragma unroll
            for (int gg = 0; gg < 8; gg++) hsum += s->part[gg][k];
            s->htld[k] = hsum;
            asm volatile("bar.sync 1, 64;" ::: "memory");
            ull A2a = 0, A2b = 0, A3a = 0, A3b = 0;
            const float* w2p = s->W2hT + k * WP;
            const float* w3p = s->W3hT + k * WP;
#pragma unroll
            for (int q = 0; q < 16; q++) {
                ulonglong2 hp = *(const ulonglong2*)(s->htld + 4 * q);
                ulonglong2 w2v = *(const ulonglong2*)(w2p + 4 * q);
                ulonglong2 w3v = *(const ulonglong2*)(w3p + 4 * q);
                A2a = fma2(hp.x, w2v.x, A2a); A2b = fma2(hp.y, w2v.y, A2b);
                A3a = fma2(hp.x, w3v.x, A3a); A3b = fma2(hp.y, w3v.y, A3b);
            }
            float a2 = a2pre + f2sum(A2a) + f2sum(A2b);
            float a3 = a3pre + f2sum(A3a) + f2sum(A3b);
            s->LGs[k] = fsig(a3) * fsig(2.0f * a2);   // (tanh+1)/2 == sigmoid(2x)
            asm volatile("bar.sync 1, 64;" ::: "memory");
            // lgt = b4 + LG @ W4b
            ull La = 0, Lb = 0;
            const float* wbp = s->W4bT + k * WP;
#pragma unroll
            for (int q = 0; q < 16; q++) {
                ulonglong2 lg = *(const ulonglong2*)(s->LGs + 4 * q);
                ulonglong2 w = *(const ulonglong2*)(wbp + 4 * q);
                La = fma2(lg.x, w.x, La); Lb = fma2(lg.y, w.y, Lb);
            }
            s->lgt[k] = s->b4s[k] + f2sum(La) + f2sum(Lb);
            if (t + 1 < S - 1) {
                a2pre = d_P2[(b * (S - 1) + t + 1) * K + tid];
                a3pre = d_P3[(b * (S - 1) + t + 1) * K + tid];
            }
            mm_q<4>(s, hcur, r0, qoff, wreg, acc, odd, lane);
        } else if (wid == 2) {
            // ==== y_t partial over own 64 rows; rank0 flushes out[t-1] ====
            float pt = 0.0f;
            if (t > 0) {
                ull Aa = 0, Ab = 0, Ba = 0, Bb = 0;
                const float* rr0 = hcur + lane * HP;
                const float* rr1 = hcur + (lane + 32) * HP;
#pragma unroll
                for (int q = 0; q < 16; q++) {
                    ulonglong2 wv = *(const ulonglong2*)(s->Wabs + 4 * q);
                    ulonglong2 h0v = *(const ulonglong2*)(rr0 + 4 * q);
                    ulonglong2 h1v = *(const ulonglong2*)(rr1 + 4 * q);
                    Aa = fma2(h0v.x, wv.x, Aa); Ab = fma2(h0v.y, wv.y, Ab);
                    Ba = fma2(h1v.x, wv.x, Ba); Bb = fma2(h1v.y, wv.y, Bb);
                }
                int g0 = rankoff + lane, g1 = g0 + 32;
                float abl0 = fsig(f2sum(Aa) + f2sum(Ab) + bab0) * s->qrow[t3][g0];
                float abl1 = fsig(f2sum(Ba) + f2sum(Bb) + bab0) * s->qrow[t3][g1];
                pt = s->discs[cb] *
                     ((abl0 - s->diffr[cb][g0]) + (abl1 - s->diffr[cb][g1]));
#pragma unroll
                for (int off = 16; off; off >>= 1)
                    pt += __shfl_xor_sync(0xffffffffu, pt, off);
            }
            if (rank == 1) {
                if (t > 0 && lane == 0) {
                    remote_st32(s2u(&s->ypeer[cb]), peer, pt);
                    remote_arrive(s2u(&s->mb_y[cb]), peer);
                }
            } else {
                if (t > 1 && lane == 0) {
                    int pb = (t - 1) & 1;
                    mbar_wait_acq(s2u(&s->mb_y[pb]), (uint32_t)(((t - 2) >> 1) & 1));
                    out[b * S + t - 1] = fsig(ypprev + s->ypeer[pb]);
                }
                ypprev = pt;
            }
            mm_q<6>(s, hcur, r0, qoff, wreg, acc, odd, lane);
        } else if (wid == 3) {
            // ==== prefetch next q rows / diff / disc ====
            int t2 = (t + 2 < S) ? (t + 2) : (S - 1);
            int q2v = qseq[b * S + t2];
            int q1v = qseq[b * S + t + 1];
#pragma unroll
            for (int h = 0; h < 2; h++) {
                int i2 = lane + 32 * h;
                *(float2*)(s->qrow[(t + 2) % 3] + 2 * i2) =
                    *(const float2*)(qmat + q2v * C + 2 * i2);
                *(float2*)(s->diffr[nb] + 2 * i2) =
                    *(const float2*)(d_diffQ + q1v * C + 2 * i2);
            }
            if (lane == 0) s->discs[nb] = d_discQ[q1v];
            mm_q<6>(s, hcur, r0, qoff, wreg, acc, odd, lane);
        } else {
            mm_q<9>(s, hcur, r0, qoff, wreg, acc, odd, lane);
        }
        __syncthreads();   // sync1: LGs/lgt ready, q-high partials stored

        // ==== epilogue on even warps only ====
        if (!odd) {
            if (pr == 0)      epi_q<4>(s, hcur, hnew, r0, lane, pr, rankoff, t3, t3n, acc);
            else if (pr == 1) epi_q<6>(s, hcur, hnew, r0, lane, pr, rankoff, t3, t3n, acc);
            else              epi_q<9>(s, hcur, hnew, r0, lane, pr, rankoff, t3, t3n, acc);
        }
        __syncthreads();   // sync2: hnew + part complete

        // ---- send summed h_tilde partial for step t+1 to peer ----
        if (wid == 13 && lane < 16 && t < S - 2) {
            int base = lane * 4;
            float4 p = *(const float4*)&s->part[0][base];
#pragma unroll
            for (int gg = 1; gg < 8; gg++) {
                float4 t4 = *(const float4*)&s->part[gg][base];
                p.x += t4.x; p.y += t4.y; p.z += t4.z; p.w += t4.w;
            }
            uint32_t dst = s2u(&s->htpeer[nb][base]);
            remote_st64(dst, peer, packf2(p.x, p.y));
            remote_st64(dst + 8, peer, packf2(p.z, p.w));
            remote_arrive(s2u(&s->mb_ht[nb]), peer);
        }
    }

    // ==== tail ====
    if (wid == 2) {
        // flush out[S-2] on rank0
        if (rank == 0 && lane == 0) {
            int pb = (S - 2) & 1;   // 0
            mbar_wait_acq(s2u(&s->mb_y[pb]), (uint32_t)(((S - 3) >> 1) & 1));
            out[b * S + (S - 2)] = fsig(ypprev + s->ypeer[pb]);
        }
        // final y_{S-1} on h state hs[1]
        const float* hfin = s->hs[(S - 1) & 1];
        ull Aa = 0, Ab = 0, Ba = 0, Bb = 0;
        const float* rr0 = hfin + lane * HP;
        const float* rr1 = hfin + (lane + 32) * HP;
#pragma unroll
        for (int q = 0; q < 16; q++) {
            ulonglong2 wv = *(const ulonglong2*)(s->Wabs + 4 * q);
            ulonglong2 h0v = *(const ulonglong2*)(rr0 + 4 * q);
            ulonglong2 h1v = *(const ulonglong2*)(rr1 + 4 * q);
            Aa = fma2(h0v.x, wv.x, Aa); Ab = fma2(h0v.y, wv.y, Ab);
            Ba = fma2(h1v.x, wv.x, Ba); Bb = fma2(h1v.y, wv.y, Bb);
        }
        int g0 = rankoff + lane, g1 = g0 + 32;
        float abl0 = fsig(f2sum(Aa) + f2sum(Ab) + bab0) * s->qrow[(S - 1) % 3][g0];
        float abl1 = fsig(f2sum(Ba) + f2sum(Bb) + bab0) * s->qrow[(S - 1) % 3][g1];
        float pt = s->discs[1] *
                   ((abl0 - s->diffr[1][g0]) + (abl1 - s->diffr[1][g1]));
#pragma unroll
        for (int off = 16; off; off >>= 1)
            pt += __shfl_xor_sync(0xffffffffu, pt, off);
        if (lane == 0) {
            if (rank == 1) {
                remote_st32(s2u(&s->ypeer[1]), peer, pt);
                remote_arrive(s2u(&s->mb_y[1]), peer);
            } else {
                mbar_wait_acq(s2u(&s->mb_y[1]), (uint32_t)(((S - 2) >> 1) & 1));
                out[b * S + S - 1] = fsig(pt + s->ypeer[1]);
            }
        }
    }
    CLUSTER_SYNC_();   // keep smem alive for in-flight peer ops
}

// -------- launch --------
extern "C" void kernel_launch(void* const* d_in, const int* in_sizes, int n_in,
                              void* d_out, int out_size) {
    const int*   qseq  = (const int*)d_in[0];
    const int*   cseq  = (const int*)d_in[1];
    const float* qmat  = (const float*)d_in[2];
    const float* Eq    = (const float*)d_in[3];
    const float* Ec    = (const float*)d_in[4];
    const float* h0    = (const float*)d_in[5];
    const float* W1    = (const float*)d_in[6];
    const float* b1    = (const float*)d_in[7];
    const float* W2    = (const float*)d_in[8];
    const float* b2    = (const float*)d_in[9];
    const float* W3    = (const float*)d_in[10];
    const float* b3    = (const float*)d_in[11];
    const float* W4    = (const float*)d_in[12];
    const float* b4    = (const float*)d_in[13];
    const float* Wab   = (const float*)d_in[14];
    const float* bab   = (const float*)d_in[15];
    const float* Wdiff = (const float*)d_in[16];
    const float* bdiff = (const float*)d_in[17];
    const float* Wdisc = (const float*)d_in[18];
    const float* bdisc = (const float*)d_in[19];
    float* out = (float*)d_out;

    k_al<<<NQ, 128>>>(Eq, Ec, W1, b1);
    k_dq<<<NQ, 128>>>(Eq, Wdiff, bdiff, Wdisc, bdisc, qmat);
    k_p23<<<B * (S - 1), 128>>>(qseq, cseq, W2, W3, b2, b3);

    cudaFuncSetAttribute(lpkt_main, cudaFuncAttributeMaxDynamicSharedMemorySize,
                         (int)sizeof(Smem));
    lpkt_main<<<2 * B, 512, sizeof(Smem)>>>(qseq, qmat, h0, W2, W3, W4, b4, Wab, bab, out);
}